// round 16
// baseline (speedup 1.0000x reference)
#include <cuda_runtime.h>
#include <math.h>

// Shapes (fixed by the problem)
#define BB   128
#define NN   32
#define MM   64
#define OBS_ 128
#define ACT_ 16
#define DQK_ 128
#define DAV_ 64
#define HID_ 64

// Output offsets: value [B,N,N,1] | weight [B,N,N] | weight_other [B,N,M]
#define OFF_VAL 0
#define OFF_W   (BB * NN * NN)            // 131072
#define OFF_WO  (2 * BB * NN * NN)        // 262144

// Row strides: multiples of 4 floats (16B-aligned rows for LDS.128) with an
// ODD float4 stride (33 / 17 / 9) -> conflict-free row-per-lane vector access.
#define SD 132    // 33 float4
#define MD 68     // 17 float4
#define WD 36     // 9  float4

struct Smem {
    float s[32][SD];         // states[b]
    float so[64][SD];        // states_other[b]
    float ko_[32][SD];       // key_obs
    float qo_[32][SD];       // query_obs (pre-scaled by 1/sqrt(dk))
    float qa[32][SD];        // query_agent (pre-scaled)
    float keys_o[64][SD];    // keys_other
    float av_act[32][MD];
    float delta[32][MD];     // tanh(av_pol) - tanh(av_act)
    float base_[32][MD];     // weight @ av_act
    float w_o[32][MD];       // logits_other -> softmax weight_other
    float av_o[64][MD];
    float wav_o[32][MD];
    float u[32][MD];
    float v[32][MD];
    float w[32][WD];         // logits -> softmax weight
    float act[32][16];
    float pol[32][16];
    float act_o[64][16];
    float wf2[64];
};

__device__ __forceinline__ float warp_max(float x) {
    #pragma unroll
    for (int off = 16; off; off >>= 1)
        x = fmaxf(x, __shfl_xor_sync(0xffffffffu, x, off));
    return x;
}
__device__ __forceinline__ float warp_sum(float x) {
    #pragma unroll
    for (int off = 16; off; off >>= 1)
        x += __shfl_xor_sync(0xffffffffu, x, off);
    return x;
}
__device__ __forceinline__ float dot4(float4 a, float4 b, float acc) {
    acc = fmaf(a.x, b.x, acc);
    acc = fmaf(a.y, b.y, acc);
    acc = fmaf(a.z, b.z, acc);
    acc = fmaf(a.w, b.w, acc);
    return acc;
}

__global__ __launch_bounds__(512, 1)
void critic_dual_attn_kernel(const float* __restrict__ states,
                             const float* __restrict__ policies,
                             const float* __restrict__ actions,
                             const float* __restrict__ states_other,
                             const float* __restrict__ actions_other,
                             const float* __restrict__ W_key,
                             const float* __restrict__ W_query,
                             const float* __restrict__ W_av,
                             const float* __restrict__ W_key_other,
                             const float* __restrict__ W_query_other,
                             const float* __restrict__ W_av_other,
                             const float* __restrict__ W_f1,
                             const float* __restrict__ W_f2,
                             float* __restrict__ out)
{
    extern __shared__ char smem_raw[];
    Smem& sm = *reinterpret_cast<Smem*>(smem_raw);

    const int b    = blockIdx.x;
    const int tid  = threadIdx.x;
    const int lane = tid & 31;
    const int warp = tid >> 5;               // 0..15
    const float scale = 0.08838834764831845f;   // 1/sqrt(128)

    // ================= Phase A: float4 loads of all per-batch inputs =================
    {
        const float4* S4 = reinterpret_cast<const float4*>(states + b * NN * OBS_);
        for (int idx = tid; idx < NN * 32; idx += 512)               // 1024 f4
            *reinterpret_cast<float4*>(&sm.s[idx >> 5][(idx & 31) * 4]) = S4[idx];
        const float4* SO4 = reinterpret_cast<const float4*>(states_other + b * MM * OBS_);
        for (int idx = tid; idx < MM * 32; idx += 512)               // 2048 f4
            *reinterpret_cast<float4*>(&sm.so[idx >> 5][(idx & 31) * 4]) = SO4[idx];
        const float4* A4 = reinterpret_cast<const float4*>(actions  + b * NN * ACT_);
        const float4* P4 = reinterpret_cast<const float4*>(policies + b * NN * ACT_);
        for (int idx = tid; idx < NN * 4; idx += 512) {              // 128 f4
            *reinterpret_cast<float4*>(&sm.act[idx >> 2][(idx & 3) * 4]) = A4[idx];
            *reinterpret_cast<float4*>(&sm.pol[idx >> 2][(idx & 3) * 4]) = P4[idx];
        }
        const float4* AO4 = reinterpret_cast<const float4*>(actions_other + b * MM * ACT_);
        for (int idx = tid; idx < MM * 4; idx += 512)                // 256 f4
            *reinterpret_cast<float4*>(&sm.act_o[idx >> 2][(idx & 3) * 4]) = AO4[idx];
        if (tid < 16)
            *reinterpret_cast<float4*>(&sm.wf2[tid * 4]) =
                reinterpret_cast<const float4*>(W_f2)[tid];
    }
    __syncthreads();

    // ============ Phase P1: all input-only matmuls, no intervening syncs ============
    // Weight LDGs chunk-prefetched (MLP 8-16); SMEM streams are LDS.128.

    {   // B1: key_obs & query_obs  [32,128]  (4 grp x 8 rows), chunk 8 dual-stream
        const int o  = tid & 127;
        const int ih = tid >> 7;             // 0..3
        const float* __restrict__ Wk = W_key   + o;
        const float* __restrict__ Wq = W_query + o;
        float aK[8], aQ[8];
        #pragma unroll
        for (int r = 0; r < 8; r++) { aK[r] = 0.f; aQ[r] = 0.f; }
        #pragma unroll 1
        for (int kk = 0; kk < OBS_; kk += 8) {
            float cK[8], cQ[8];
            #pragma unroll
            for (int t = 0; t < 8; t++) {
                cK[t] = Wk[(kk + t) * DQK_];
                cQ[t] = Wq[(kk + t) * DQK_];
            }
            #pragma unroll
            for (int r = 0; r < 8; r++) {
                const float4 s0 = *reinterpret_cast<const float4*>(&sm.s[ih * 8 + r][kk]);
                const float4 s1 = *reinterpret_cast<const float4*>(&sm.s[ih * 8 + r][kk + 4]);
                const float sv[8] = {s0.x, s0.y, s0.z, s0.w, s1.x, s1.y, s1.z, s1.w};
                #pragma unroll
                for (int t = 0; t < 8; t++) {
                    aK[r] = fmaf(sv[t], cK[t], aK[r]);
                    aQ[r] = fmaf(sv[t], cQ[t], aQ[r]);
                }
            }
        }
        #pragma unroll
        for (int r = 0; r < 8; r++) {
            sm.ko_[ih * 8 + r][o] = aK[r];
            sm.qo_[ih * 8 + r][o] = aQ[r] * scale;
        }
    }

    {   // B2: query_agent = states @ W_query_other  [32,128]  (4 grp x 8 rows), chunk 16
        const int o  = tid & 127;
        const int ih = tid >> 7;
        const float* __restrict__ Wq = W_query_other + o;
        float a[8];
        #pragma unroll
        for (int r = 0; r < 8; r++) a[r] = 0.f;
        #pragma unroll 1
        for (int kk = 0; kk < OBS_; kk += 16) {
            float c[16];
            #pragma unroll
            for (int t = 0; t < 16; t++) c[t] = Wq[(kk + t) * DQK_];
            #pragma unroll
            for (int r = 0; r < 8; r++) {
                const float4 s0 = *reinterpret_cast<const float4*>(&sm.s[ih * 8 + r][kk]);
                const float4 s1 = *reinterpret_cast<const float4*>(&sm.s[ih * 8 + r][kk + 4]);
                const float4 s2 = *reinterpret_cast<const float4*>(&sm.s[ih * 8 + r][kk + 8]);
                const float4 s3 = *reinterpret_cast<const float4*>(&sm.s[ih * 8 + r][kk + 12]);
                const float sv[16] = {s0.x, s0.y, s0.z, s0.w, s1.x, s1.y, s1.z, s1.w,
                                      s2.x, s2.y, s2.z, s2.w, s3.x, s3.y, s3.z, s3.w};
                #pragma unroll
                for (int t = 0; t < 16; t++)
                    a[r] = fmaf(sv[t], c[t], a[r]);
            }
        }
        #pragma unroll
        for (int r = 0; r < 8; r++) sm.qa[ih * 8 + r][o] = a[r] * scale;
    }

    {   // B3: keys_other = states_other @ W_key_other  [64,128] (4 grp x 16 rows), chunk 8
        const int o  = tid & 127;
        const int ih = tid >> 7;             // 0..3
        const float* __restrict__ Wk = W_key_other + o;
        float a[16];
        #pragma unroll
        for (int r = 0; r < 16; r++) a[r] = 0.f;
        #pragma unroll 1
        for (int kk = 0; kk < OBS_; kk += 8) {
            float c[8];
            #pragma unroll
            for (int t = 0; t < 8; t++) c[t] = Wk[(kk + t) * DQK_];
            #pragma unroll
            for (int r = 0; r < 16; r++) {
                const float4 s0 = *reinterpret_cast<const float4*>(&sm.so[ih * 16 + r][kk]);
                const float4 s1 = *reinterpret_cast<const float4*>(&sm.so[ih * 16 + r][kk + 4]);
                const float sv[8] = {s0.x, s0.y, s0.z, s0.w, s1.x, s1.y, s1.z, s1.w};
                #pragma unroll
                for (int t = 0; t < 8; t++)
                    a[r] = fmaf(sv[t], c[t], a[r]);
            }
        }
        #pragma unroll
        for (int r = 0; r < 16; r++) sm.keys_o[ih * 16 + r][o] = a[r];
    }

    {   // B4: av_act / delta  [32,64]  (8 grp x 4 rows), chunk 16
        const int o = tid & 63;
        const int g = tid >> 6;              // 0..7
        const float* __restrict__ Wv = W_av + o;
        float aS[4];
        #pragma unroll
        for (int r = 0; r < 4; r++) aS[r] = 0.f;
        #pragma unroll 1
        for (int kk = 0; kk < OBS_; kk += 16) {
            float c[16];
            #pragma unroll
            for (int t = 0; t < 16; t++) c[t] = Wv[(kk + t) * DAV_];
            #pragma unroll
            for (int r = 0; r < 4; r++) {
                const float4 s0 = *reinterpret_cast<const float4*>(&sm.s[g * 4 + r][kk]);
                const float4 s1 = *reinterpret_cast<const float4*>(&sm.s[g * 4 + r][kk + 4]);
                const float4 s2 = *reinterpret_cast<const float4*>(&sm.s[g * 4 + r][kk + 8]);
                const float4 s3 = *reinterpret_cast<const float4*>(&sm.s[g * 4 + r][kk + 12]);
                const float sv[16] = {s0.x, s0.y, s0.z, s0.w, s1.x, s1.y, s1.z, s1.w,
                                      s2.x, s2.y, s2.z, s2.w, s3.x, s3.y, s3.z, s3.w};
                #pragma unroll
                for (int t = 0; t < 16; t++)
                    aS[r] = fmaf(sv[t], c[t], aS[r]);
            }
        }
        float aA[4], aP[4];
        #pragma unroll
        for (int r = 0; r < 4; r++) { aA[r] = aS[r]; aP[r] = aS[r]; }
        {
            float c[16];
            #pragma unroll
            for (int t = 0; t < 16; t++) c[t] = Wv[(OBS_ + t) * DAV_];
            #pragma unroll
            for (int r = 0; r < 4; r++) {
                const float4 a0 = *reinterpret_cast<const float4*>(&sm.act[g * 4 + r][0]);
                const float4 a1 = *reinterpret_cast<const float4*>(&sm.act[g * 4 + r][4]);
                const float4 a2 = *reinterpret_cast<const float4*>(&sm.act[g * 4 + r][8]);
                const float4 a3 = *reinterpret_cast<const float4*>(&sm.act[g * 4 + r][12]);
                const float4 p0 = *reinterpret_cast<const float4*>(&sm.pol[g * 4 + r][0]);
                const float4 p1 = *reinterpret_cast<const float4*>(&sm.pol[g * 4 + r][4]);
                const float4 p2 = *reinterpret_cast<const float4*>(&sm.pol[g * 4 + r][8]);
                const float4 p3 = *reinterpret_cast<const float4*>(&sm.pol[g * 4 + r][12]);
                const float av[16] = {a0.x, a0.y, a0.z, a0.w, a1.x, a1.y, a1.z, a1.w,
                                      a2.x, a2.y, a2.z, a2.w, a3.x, a3.y, a3.z, a3.w};
                const float pv[16] = {p0.x, p0.y, p0.z, p0.w, p1.x, p1.y, p1.z, p1.w,
                                      p2.x, p2.y, p2.z, p2.w, p3.x, p3.y, p3.z, p3.w};
                #pragma unroll
                for (int t = 0; t < 16; t++) {
                    aA[r] = fmaf(av[t], c[t], aA[r]);
                    aP[r] = fmaf(pv[t], c[t], aP[r]);
                }
            }
        }
        #pragma unroll
        for (int r = 0; r < 4; r++) {
            float ta = tanhf(aA[r]);
            sm.av_act[g * 4 + r][o] = ta;
            sm.delta[g * 4 + r][o]  = tanhf(aP[r]) - ta;
        }
    }

    {   // B5: av_other = tanh([so|act_o] @ W_av_other)  [64,64] (8 grp x 8 rows), chunk 16
        const int o = tid & 63;
        const int g = tid >> 6;              // 0..7
        const float* __restrict__ Wv = W_av_other + o;
        float a[8];
        #pragma unroll
        for (int r = 0; r < 8; r++) a[r] = 0.f;
        #pragma unroll 1
        for (int kk = 0; kk < OBS_; kk += 16) {
            float c[16];
            #pragma unroll
            for (int t = 0; t < 16; t++) c[t] = Wv[(kk + t) * DAV_];
            #pragma unroll
            for (int r = 0; r < 8; r++) {
                const float4 s0 = *reinterpret_cast<const float4*>(&sm.so[g * 8 + r][kk]);
                const float4 s1 = *reinterpret_cast<const float4*>(&sm.so[g * 8 + r][kk + 4]);
                const float4 s2 = *reinterpret_cast<const float4*>(&sm.so[g * 8 + r][kk + 8]);
                const float4 s3 = *reinterpret_cast<const float4*>(&sm.so[g * 8 + r][kk + 12]);
                const float sv[16] = {s0.x, s0.y, s0.z, s0.w, s1.x, s1.y, s1.z, s1.w,
                                      s2.x, s2.y, s2.z, s2.w, s3.x, s3.y, s3.z, s3.w};
                #pragma unroll
                for (int t = 0; t < 16; t++)
                    a[r] = fmaf(sv[t], c[t], a[r]);
            }
        }
        {
            float c[16];
            #pragma unroll
            for (int t = 0; t < 16; t++) c[t] = Wv[(OBS_ + t) * DAV_];
            #pragma unroll
            for (int r = 0; r < 8; r++) {
                const float4 a0 = *reinterpret_cast<const float4*>(&sm.act_o[g * 8 + r][0]);
                const float4 a1 = *reinterpret_cast<const float4*>(&sm.act_o[g * 8 + r][4]);
                const float4 a2 = *reinterpret_cast<const float4*>(&sm.act_o[g * 8 + r][8]);
                const float4 a3 = *reinterpret_cast<const float4*>(&sm.act_o[g * 8 + r][12]);
                const float av[16] = {a0.x, a0.y, a0.z, a0.w, a1.x, a1.y, a1.z, a1.w,
                                      a2.x, a2.y, a2.z, a2.w, a3.x, a3.y, a3.z, a3.w};
                #pragma unroll
                for (int t = 0; t < 16; t++)
                    a[r] = fmaf(av[t], c[t], a[r]);
            }
        }
        #pragma unroll
        for (int r = 0; r < 8; r++) sm.av_o[g * 8 + r][o] = tanhf(a[r]);
    }
    __syncthreads();

    // ============== Phase P2: both logit GEMMs (register-tiled, LDS.128) ==============
    {   // w[i0..i0+1][lane] : kv rows per-lane (odd f4 stride), qv broadcast
        const int j  = lane;
        const int i0 = warp * 2;
        float acc[2] = {0.f, 0.f};
        #pragma unroll 4
        for (int d = 0; d < DQK_; d += 4) {
            const float4 kv = *reinterpret_cast<const float4*>(&sm.ko_[j][d]);
            #pragma unroll
            for (int c = 0; c < 2; c++) {
                const float4 qv = *reinterpret_cast<const float4*>(&sm.qo_[i0 + c][d]);
                acc[c] = dot4(qv, kv, acc[c]);
            }
        }
        #pragma unroll
        for (int c = 0; c < 2; c++) sm.w[i0 + c][j] = acc[c];
    }
    {   // w_o[i0..i0+1][lane, lane+32]
        const int i0 = warp * 2;
        float a0[2] = {0.f, 0.f};
        float a1[2] = {0.f, 0.f};
        #pragma unroll 4
        for (int d = 0; d < DQK_; d += 4) {
            const float4 k0 = *reinterpret_cast<const float4*>(&sm.keys_o[lane][d]);
            const float4 k1 = *reinterpret_cast<const float4*>(&sm.keys_o[lane + 32][d]);
            #pragma unroll
            for (int c = 0; c < 2; c++) {
                const float4 qv = *reinterpret_cast<const float4*>(&sm.qa[i0 + c][d]);
                a0[c] = dot4(qv, k0, a0[c]);
                a1[c] = dot4(qv, k1, a1[c]);
            }
        }
        #pragma unroll
        for (int c = 0; c < 2; c++) {
            sm.w_o[i0 + c][lane]      = a0[c];
            sm.w_o[i0 + c][lane + 32] = a1[c];
        }
    }
    __syncthreads();

    // ================= Phase P3: both softmaxes (16 warps, 2 rows each) =================
    {
        const int r = warp * 2;
        #pragma unroll
        for (int c = 0; c < 2; c++) {
            float x  = sm.w[r + c][lane];
            float mx = warp_max(x);
            float e  = __expf(x - mx);
            float sv = warp_sum(e);
            float o  = e / sv;
            sm.w[r + c][lane] = o;
            out[OFF_W + b * NN * NN + (r + c) * NN + lane] = o;
        }
        #pragma unroll
        for (int c = 0; c < 2; c++) {
            float x0 = sm.w_o[r + c][lane];
            float x1 = sm.w_o[r + c][lane + 32];
            float mx = warp_max(fmaxf(x0, x1));
            float e0 = __expf(x0 - mx), e1 = __expf(x1 - mx);
            float sv = warp_sum(e0 + e1);
            float o0 = e0 / sv, o1 = e1 / sv;
            sm.w_o[r + c][lane]      = o0;
            sm.w_o[r + c][lane + 32] = o1;
            out[OFF_WO + b * NN * MM + (r + c) * MM + lane]      = o0;
            out[OFF_WO + b * NN * MM + (r + c) * MM + lane + 32] = o1;
        }
    }
    __syncthreads();

    // ======== Phase P4: base = w @ av_act, wav_o = w_o @ av_o (hoisted av, w as f4) ========
    {
        const int o = tid & 63;
        const int g = tid >> 6;              // 0..7 -> 4 rows each
        float a[4];
        #pragma unroll
        for (int r = 0; r < 4; r++) a[r] = 0.f;
        #pragma unroll
        for (int kk = 0; kk < NN; kk += 4) {
            const float av0 = sm.av_act[kk + 0][o];
            const float av1 = sm.av_act[kk + 1][o];
            const float av2 = sm.av_act[kk + 2][o];
            const float av3 = sm.av_act[kk + 3][o];
            #pragma unroll
            for (int r = 0; r < 4; r++) {
                const float4 w4 = *reinterpret_cast<const float4*>(&sm.w[g * 4 + r][kk]);
                a[r] = fmaf(w4.x, av0, fmaf(w4.y, av1, fmaf(w4.z, av2, fmaf(w4.w, av3, a[r]))));
            }
        }
        #pragma unroll
        for (int r = 0; r < 4; r++) sm.base_[g * 4 + r][o] = a[r];

        float c[4];
        #pragma unroll
        for (int r = 0; r < 4; r++) c[r] = 0.f;
        #pragma unroll
        for (int mm = 0; mm < MM; mm += 4) {
            const float av0 = sm.av_o[mm + 0][o];
            const float av1 = sm.av_o[mm + 1][o];
            const float av2 = sm.av_o[mm + 2][o];
            const float av3 = sm.av_o[mm + 3][o];
            #pragma unroll
            for (int r = 0; r < 4; r++) {
                const float4 w4 = *reinterpret_cast<const float4*>(&sm.w_o[g * 4 + r][mm]);
                c[r] = fmaf(w4.x, av0, fmaf(w4.y, av1, fmaf(w4.z, av2, fmaf(w4.w, av3, c[r]))));
            }
        }
        #pragma unroll
        for (int r = 0; r < 4; r++) sm.wav_o[g * 4 + r][o] = c[r];
    }
    __syncthreads();

    // ========= Phase P5: u = [base|wav_o] @ W_f1, v = delta @ W_f1[:64] (chunk 16) =========
    {
        const int o = tid & 63;
        const int g = tid >> 6;              // 0..7 -> 4 rows each
        const float* __restrict__ Wf = W_f1 + o;
        float aU[4], aV[4];
        #pragma unroll
        for (int r = 0; r < 4; r++) { aU[r] = 0.f; aV[r] = 0.f; }
        #pragma unroll 1
        for (int kk = 0; kk < DAV_; kk += 16) {
            float c[16];
            #pragma unroll
            for (int t = 0; t < 16; t++) c[t] = Wf[(kk + t) * HID_];
            #pragma unroll
            for (int r = 0; r < 4; r++) {
                const float4 b0 = *reinterpret_cast<const float4*>(&sm.base_[g * 4 + r][kk]);
                const float4 b1 = *reinterpret_cast<const float4*>(&sm.base_[g * 4 + r][kk + 4]);
                const float4 b2 = *reinterpret_cast<const float4*>(&sm.base_[g * 4 + r][kk + 8]);
                const float4 b3 = *reinterpret_cast<const float4*>(&sm.base_[g * 4 + r][kk + 12]);
                const float4 d0 = *reinterpret_cast<const float4*>(&sm.delta[g * 4 + r][kk]);
                const float4 d1 = *reinterpret_cast<const float4*>(&sm.delta[g * 4 + r][kk + 4]);
                const float4 d2 = *reinterpret_cast<const float4*>(&sm.delta[g * 4 + r][kk + 8]);
                const float4 d3 = *reinterpret_cast<const float4*>(&sm.delta[g * 4 + r][kk + 12]);
                const float bv[16] = {b0.x, b0.y, b0.z, b0.w, b1.x, b1.y, b1.z, b1.w,
                                      b2.x, b2.y, b2.z, b2.w, b3.x, b3.y, b3.z, b3.w};
                const float dv[16] = {d0.x, d0.y, d0.z, d0.w, d1.x, d1.y, d1.z, d1.w,
                                      d2.x, d2.y, d2.z, d2.w, d3.x, d3.y, d3.z, d3.w};
                #pragma unroll
                for (int t = 0; t < 16; t++) {
                    aU[r] = fmaf(bv[t], c[t], aU[r]);
                    aV[r] = fmaf(dv[t], c[t], aV[r]);
                }
            }
        }
        #pragma unroll 1
        for (int kk = 0; kk < DAV_; kk += 16) {
            float c[16];
            #pragma unroll
            for (int t = 0; t < 16; t++) c[t] = Wf[(DAV_ + kk + t) * HID_];
            #pragma unroll
            for (int r = 0; r < 4; r++) {
                const float4 w0 = *reinterpret_cast<const float4*>(&sm.wav_o[g * 4 + r][kk]);
                const float4 w1 = *reinterpret_cast<const float4*>(&sm.wav_o[g * 4 + r][kk + 4]);
                const float4 w2 = *reinterpret_cast<const float4*>(&sm.wav_o[g * 4 + r][kk + 8]);
                const float4 w3 = *reinterpret_cast<const float4*>(&sm.wav_o[g * 4 + r][kk + 12]);
                const float wv[16] = {w0.x, w0.y, w0.z, w0.w, w1.x, w1.y, w1.z, w1.w,
                                      w2.x, w2.y, w2.z, w2.w, w3.x, w3.y, w3.z, w3.w};
                #pragma unroll
                for (int t = 0; t < 16; t++)
                    aU[r] = fmaf(wv[t], c[t], aU[r]);
            }
        }
        #pragma unroll
        for (int r = 0; r < 4; r++) {
            sm.u[g * 4 + r][o] = aU[r];
            sm.v[g * 4 + r][o] = aV[r];
        }
    }
    __syncthreads();

    // ============== Phase P6: value (register-tiled, v rows per-lane f4) ==============
    {
        const int j  = lane;
        const int i0 = warp * 2;
        float wij[2], acc[2];
        #pragma unroll
        for (int c = 0; c < 2; c++) { wij[c] = sm.w[i0 + c][j]; acc[c] = 0.f; }
        #pragma unroll 4
        for (int f = 0; f < HID_; f += 4) {
            const float4 v4 = *reinterpret_cast<const float4*>(&sm.v[j][f]);
            const float4 f2 = *reinterpret_cast<const float4*>(&sm.wf2[f]);
            #pragma unroll
            for (int c = 0; c < 2; c++) {
                const float4 u4 = *reinterpret_cast<const float4*>(&sm.u[i0 + c][f]);
                float p, l;
                p = fmaf(wij[c], v4.x, u4.x); l = p > 0.f ? p : 0.01f * p; acc[c] = fmaf(f2.x, l, acc[c]);
                p = fmaf(wij[c], v4.y, u4.y); l = p > 0.f ? p : 0.01f * p; acc[c] = fmaf(f2.y, l, acc[c]);
                p = fmaf(wij[c], v4.z, u4.z); l = p > 0.f ? p : 0.01f * p; acc[c] = fmaf(f2.z, l, acc[c]);
                p = fmaf(wij[c], v4.w, u4.w); l = p > 0.f ? p : 0.01f * p; acc[c] = fmaf(f2.w, l, acc[c]);
            }
        }
        #pragma unroll
        for (int c = 0; c < 2; c++)
            out[OFF_VAL + b * NN * NN + (i0 + c) * NN + j] = acc[c];
    }
}

extern "C" void kernel_launch(void* const* d_in, const int* in_sizes, int n_in,
                              void* d_out, int out_size) {
    const float* states        = (const float*)d_in[0];
    const float* policies      = (const float*)d_in[1];
    const float* actions       = (const float*)d_in[2];
    const float* states_other  = (const float*)d_in[3];
    const float* actions_other = (const float*)d_in[4];
    const float* W_key         = (const float*)d_in[5];
    const float* W_query       = (const float*)d_in[6];
    const float* W_av          = (const float*)d_in[7];
    const float* W_key_other   = (const float*)d_in[8];
    const float* W_query_other = (const float*)d_in[9];
    const float* W_av_other    = (const float*)d_in[10];
    const float* W_f1          = (const float*)d_in[11];
    const float* W_f2          = (const float*)d_in[12];
    float* out = (float*)d_out;

    const int smem_bytes = (int)sizeof(Smem);   // ~221 KB, 1 CTA/SM
    cudaFuncSetAttribute(critic_dual_attn_kernel,
                         cudaFuncAttributeMaxDynamicSharedMemorySize, smem_bytes);

    critic_dual_attn_kernel<<<BB, 512, smem_bytes>>>(
        states, policies, actions, states_other, actions_other,
        W_key, W_query, W_av, W_key_other, W_query_other, W_av_other,
        W_f1, W_f2, out);
}

// round 17
// speedup vs baseline: 1.0756x; 1.0756x over previous
#include <cuda_runtime.h>
#include <math.h>

// Shapes (fixed by the problem)
#define BB   128
#define NN   32
#define MM   64
#define OBS_ 128
#define ACT_ 16
#define DQK_ 128
#define DAV_ 64
#define HID_ 64

// Output offsets: value [B,N,N,1] | weight [B,N,N] | weight_other [B,N,M]
#define OFF_VAL 0
#define OFF_W   (BB * NN * NN)            // 131072
#define OFF_WO  (2 * BB * NN * NN)        // 262144

// Row strides: multiples of 4 floats (16B-aligned rows for LDS.128) with an
// ODD float4 stride (33 / 17 / 9) -> conflict-free row-per-lane vector access.
#define SD 132    // 33 float4
#define MD 68     // 17 float4
#define WD 36     // 9  float4

struct Smem {
    float s[32][SD];         // states[b]
    float so[64][SD];        // states_other[b]
    float ko_[32][SD];       // key_obs
    float qo_[32][SD];       // query_obs (pre-scaled by 1/sqrt(dk))
    float qa[32][SD];        // query_agent (pre-scaled)
    float keys_o[64][SD];    // keys_other
    float av_act[32][MD];
    float delta[32][MD];     // tanh(av_pol) - tanh(av_act)
    float base_[32][MD];     // weight @ av_act
    float w_o[32][MD];       // logits_other -> softmax weight_other
    float av_o[64][MD];
    float wav_o[32][MD];
    float u[32][MD];
    float v[32][MD];
    float w[32][WD];         // logits -> softmax weight
    float act[32][16];
    float pol[32][16];
    float act_o[64][16];
    float wf2[64];
};

typedef unsigned long long u64;

// ---- packed f32x2 helpers (FFMA2: 2 MACs / instruction) ----
__device__ __forceinline__ u64 pk2(float lo, float hi) {
    u64 r; asm("mov.b64 %0, {%1, %2};" : "=l"(r) : "f"(lo), "f"(hi)); return r;
}
__device__ __forceinline__ u64 ffma2(u64 a, u64 b, u64 c) {
    u64 d; asm("fma.rn.f32x2 %0, %1, %2, %3;" : "=l"(d) : "l"(a), "l"(b), "l"(c));
    return d;
}
__device__ __forceinline__ float hsum2(u64 v) {
    float lo, hi; asm("mov.b64 {%0, %1}, %2;" : "=f"(lo), "=f"(hi) : "l"(v));
    return lo + hi;
}

__device__ __forceinline__ float warp_max(float x) {
    #pragma unroll
    for (int off = 16; off; off >>= 1)
        x = fmaxf(x, __shfl_xor_sync(0xffffffffu, x, off));
    return x;
}
__device__ __forceinline__ float warp_sum(float x) {
    #pragma unroll
    for (int off = 16; off; off >>= 1)
        x += __shfl_xor_sync(0xffffffffu, x, off);
    return x;
}

__global__ __launch_bounds__(512, 1)
void critic_dual_attn_kernel(const float* __restrict__ states,
                             const float* __restrict__ policies,
                             const float* __restrict__ actions,
                             const float* __restrict__ states_other,
                             const float* __restrict__ actions_other,
                             const float* __restrict__ W_key,
                             const float* __restrict__ W_query,
                             const float* __restrict__ W_av,
                             const float* __restrict__ W_key_other,
                             const float* __restrict__ W_query_other,
                             const float* __restrict__ W_av_other,
                             const float* __restrict__ W_f1,
                             const float* __restrict__ W_f2,
                             float* __restrict__ out)
{
    extern __shared__ char smem_raw[];
    Smem& sm = *reinterpret_cast<Smem*>(smem_raw);

    const int b    = blockIdx.x;
    const int tid  = threadIdx.x;
    const int lane = tid & 31;
    const int warp = tid >> 5;               // 0..15
    const float scale = 0.08838834764831845f;   // 1/sqrt(128)

    // ================= Phase A: float4 loads of all per-batch inputs =================
    {
        const float4* S4 = reinterpret_cast<const float4*>(states + b * NN * OBS_);
        for (int idx = tid; idx < NN * 32; idx += 512)
            *reinterpret_cast<float4*>(&sm.s[idx >> 5][(idx & 31) * 4]) = S4[idx];
        const float4* SO4 = reinterpret_cast<const float4*>(states_other + b * MM * OBS_);
        for (int idx = tid; idx < MM * 32; idx += 512)
            *reinterpret_cast<float4*>(&sm.so[idx >> 5][(idx & 31) * 4]) = SO4[idx];
        const float4* A4 = reinterpret_cast<const float4*>(actions  + b * NN * ACT_);
        const float4* P4 = reinterpret_cast<const float4*>(policies + b * NN * ACT_);
        for (int idx = tid; idx < NN * 4; idx += 512) {
            *reinterpret_cast<float4*>(&sm.act[idx >> 2][(idx & 3) * 4]) = A4[idx];
            *reinterpret_cast<float4*>(&sm.pol[idx >> 2][(idx & 3) * 4]) = P4[idx];
        }
        const float4* AO4 = reinterpret_cast<const float4*>(actions_other + b * MM * ACT_);
        for (int idx = tid; idx < MM * 4; idx += 512)
            *reinterpret_cast<float4*>(&sm.act_o[idx >> 2][(idx & 3) * 4]) = AO4[idx];
        if (tid < 16)
            *reinterpret_cast<float4*>(&sm.wf2[tid * 4]) =
                reinterpret_cast<const float4*>(W_f2)[tid];
    }
    __syncthreads();

    // ============ Phase P1: all input-only matmuls, no intervening syncs ============
    // Weight LDGs chunk-prefetched; SMEM streams are LDS.128 read as f32x2 pairs.

    {   // B1: key_obs & query_obs  [32,128]  (4 grp x 8 rows), chunk 8 dual-stream
        const int o  = tid & 127;
        const int ih = tid >> 7;             // 0..3
        const float* __restrict__ Wk = W_key   + o;
        const float* __restrict__ Wq = W_query + o;
        u64 aK[8], aQ[8];
        #pragma unroll
        for (int r = 0; r < 8; r++) { aK[r] = 0ull; aQ[r] = 0ull; }
        #pragma unroll 1
        for (int kk = 0; kk < OBS_; kk += 8) {
            float cK[8], cQ[8];
            #pragma unroll
            for (int t = 0; t < 8; t++) {
                cK[t] = Wk[(kk + t) * DQK_];
                cQ[t] = Wq[(kk + t) * DQK_];
            }
            u64 cK2[4], cQ2[4];
            #pragma unroll
            for (int t = 0; t < 4; t++) {
                cK2[t] = pk2(cK[2 * t], cK[2 * t + 1]);
                cQ2[t] = pk2(cQ[2 * t], cQ[2 * t + 1]);
            }
            #pragma unroll
            for (int r = 0; r < 8; r++) {
                const ulonglong2 s01 = *reinterpret_cast<const ulonglong2*>(&sm.s[ih * 8 + r][kk]);
                const ulonglong2 s23 = *reinterpret_cast<const ulonglong2*>(&sm.s[ih * 8 + r][kk + 4]);
                aK[r] = ffma2(s01.x, cK2[0], aK[r]);
                aK[r] = ffma2(s01.y, cK2[1], aK[r]);
                aK[r] = ffma2(s23.x, cK2[2], aK[r]);
                aK[r] = ffma2(s23.y, cK2[3], aK[r]);
                aQ[r] = ffma2(s01.x, cQ2[0], aQ[r]);
                aQ[r] = ffma2(s01.y, cQ2[1], aQ[r]);
                aQ[r] = ffma2(s23.x, cQ2[2], aQ[r]);
                aQ[r] = ffma2(s23.y, cQ2[3], aQ[r]);
            }
        }
        #pragma unroll
        for (int r = 0; r < 8; r++) {
            sm.ko_[ih * 8 + r][o] = hsum2(aK[r]);
            sm.qo_[ih * 8 + r][o] = hsum2(aQ[r]) * scale;
        }
    }

    {   // B2: query_agent = states @ W_query_other  [32,128]  (4 grp x 8 rows), chunk 16
        const int o  = tid & 127;
        const int ih = tid >> 7;
        const float* __restrict__ Wq = W_query_other + o;
        u64 a[8];
        #pragma unroll
        for (int r = 0; r < 8; r++) a[r] = 0ull;
        #pragma unroll 1
        for (int kk = 0; kk < OBS_; kk += 16) {
            float c[16];
            #pragma unroll
            for (int t = 0; t < 16; t++) c[t] = Wq[(kk + t) * DQK_];
            u64 c2[8];
            #pragma unroll
            for (int t = 0; t < 8; t++) c2[t] = pk2(c[2 * t], c[2 * t + 1]);
            #pragma unroll
            for (int r = 0; r < 8; r++) {
                const ulonglong2 s01 = *reinterpret_cast<const ulonglong2*>(&sm.s[ih * 8 + r][kk]);
                const ulonglong2 s23 = *reinterpret_cast<const ulonglong2*>(&sm.s[ih * 8 + r][kk + 4]);
                const ulonglong2 s45 = *reinterpret_cast<const ulonglong2*>(&sm.s[ih * 8 + r][kk + 8]);
                const ulonglong2 s67 = *reinterpret_cast<const ulonglong2*>(&sm.s[ih * 8 + r][kk + 12]);
                a[r] = ffma2(s01.x, c2[0], a[r]);
                a[r] = ffma2(s01.y, c2[1], a[r]);
                a[r] = ffma2(s23.x, c2[2], a[r]);
                a[r] = ffma2(s23.y, c2[3], a[r]);
                a[r] = ffma2(s45.x, c2[4], a[r]);
                a[r] = ffma2(s45.y, c2[5], a[r]);
                a[r] = ffma2(s67.x, c2[6], a[r]);
                a[r] = ffma2(s67.y, c2[7], a[r]);
            }
        }
        #pragma unroll
        for (int r = 0; r < 8; r++) sm.qa[ih * 8 + r][o] = hsum2(a[r]) * scale;
    }

    {   // B3: keys_other = states_other @ W_key_other  [64,128] (4 grp x 16 rows), chunk 8
        const int o  = tid & 127;
        const int ih = tid >> 7;             // 0..3
        const float* __restrict__ Wk = W_key_other + o;
        u64 a[16];
        #pragma unroll
        for (int r = 0; r < 16; r++) a[r] = 0ull;
        #pragma unroll 1
        for (int kk = 0; kk < OBS_; kk += 8) {
            float c[8];
            #pragma unroll
            for (int t = 0; t < 8; t++) c[t] = Wk[(kk + t) * DQK_];
            u64 c2[4];
            #pragma unroll
            for (int t = 0; t < 4; t++) c2[t] = pk2(c[2 * t], c[2 * t + 1]);
            #pragma unroll
            for (int r = 0; r < 16; r++) {
                const ulonglong2 s01 = *reinterpret_cast<const ulonglong2*>(&sm.so[ih * 16 + r][kk]);
                const ulonglong2 s23 = *reinterpret_cast<const ulonglong2*>(&sm.so[ih * 16 + r][kk + 4]);
                a[r] = ffma2(s01.x, c2[0], a[r]);
                a[r] = ffma2(s01.y, c2[1], a[r]);
                a[r] = ffma2(s23.x, c2[2], a[r]);
                a[r] = ffma2(s23.y, c2[3], a[r]);
            }
        }
        #pragma unroll
        for (int r = 0; r < 16; r++) sm.keys_o[ih * 16 + r][o] = hsum2(a[r]);
    }

    {   // B4: av_act / delta  [32,64]  (8 grp x 4 rows), chunk 16
        const int o = tid & 63;
        const int g = tid >> 6;              // 0..7
        const float* __restrict__ Wv = W_av + o;
        u64 aS[4];
        #pragma unroll
        for (int r = 0; r < 4; r++) aS[r] = 0ull;
        #pragma unroll 1
        for (int kk = 0; kk < OBS_; kk += 16) {
            float c[16];
            #pragma unroll
            for (int t = 0; t < 16; t++) c[t] = Wv[(kk + t) * DAV_];
            u64 c2[8];
            #pragma unroll
            for (int t = 0; t < 8; t++) c2[t] = pk2(c[2 * t], c[2 * t + 1]);
            #pragma unroll
            for (int r = 0; r < 4; r++) {
                const ulonglong2 s01 = *reinterpret_cast<const ulonglong2*>(&sm.s[g * 4 + r][kk]);
                const ulonglong2 s23 = *reinterpret_cast<const ulonglong2*>(&sm.s[g * 4 + r][kk + 4]);
                const ulonglong2 s45 = *reinterpret_cast<const ulonglong2*>(&sm.s[g * 4 + r][kk + 8]);
                const ulonglong2 s67 = *reinterpret_cast<const ulonglong2*>(&sm.s[g * 4 + r][kk + 12]);
                aS[r] = ffma2(s01.x, c2[0], aS[r]);
                aS[r] = ffma2(s01.y, c2[1], aS[r]);
                aS[r] = ffma2(s23.x, c2[2], aS[r]);
                aS[r] = ffma2(s23.y, c2[3], aS[r]);
                aS[r] = ffma2(s45.x, c2[4], aS[r]);
                aS[r] = ffma2(s45.y, c2[5], aS[r]);
                aS[r] = ffma2(s67.x, c2[6], aS[r]);
                aS[r] = ffma2(s67.y, c2[7], aS[r]);
            }
        }
        u64 aA[4], aP[4];
        #pragma unroll
        for (int r = 0; r < 4; r++) { aA[r] = aS[r]; aP[r] = aS[r]; }
        {
            float c[16];
            #pragma unroll
            for (int t = 0; t < 16; t++) c[t] = Wv[(OBS_ + t) * DAV_];
            u64 c2[8];
            #pragma unroll
            for (int t = 0; t < 8; t++) c2[t] = pk2(c[2 * t], c[2 * t + 1]);
            #pragma unroll
            for (int r = 0; r < 4; r++) {
                const ulonglong2 a01 = *reinterpret_cast<const ulonglong2*>(&sm.act[g * 4 + r][0]);
                const ulonglong2 a23 = *reinterpret_cast<const ulonglong2*>(&sm.act[g * 4 + r][4]);
                const ulonglong2 a45 = *reinterpret_cast<const ulonglong2*>(&sm.act[g * 4 + r][8]);
                const ulonglong2 a67 = *reinterpret_cast<const ulonglong2*>(&sm.act[g * 4 + r][12]);
                const ulonglong2 p01 = *reinterpret_cast<const ulonglong2*>(&sm.pol[g * 4 + r][0]);
                const ulonglong2 p23 = *reinterpret_cast<const ulonglong2*>(&sm.pol[g * 4 + r][4]);
                const ulonglong2 p45 = *reinterpret_cast<const ulonglong2*>(&sm.pol[g * 4 + r][8]);
                const ulonglong2 p67 = *reinterpret_cast<const ulonglong2*>(&sm.pol[g * 4 + r][12]);
                aA[r] = ffma2(a01.x, c2[0], aA[r]);
                aA[r] = ffma2(a01.y, c2[1], aA[r]);
                aA[r] = ffma2(a23.x, c2[2], aA[r]);
                aA[r] = ffma2(a23.y, c2[3], aA[r]);
                aA[r] = ffma2(a45.x, c2[4], aA[r]);
                aA[r] = ffma2(a45.y, c2[5], aA[r]);
                aA[r] = ffma2(a67.x, c2[6], aA[r]);
                aA[r] = ffma2(a67.y, c2[7], aA[r]);
                aP[r] = ffma2(p01.x, c2[0], aP[r]);
                aP[r] = ffma2(p01.y, c2[1], aP[r]);
                aP[r] = ffma2(p23.x, c2[2], aP[r]);
                aP[r] = ffma2(p23.y, c2[3], aP[r]);
                aP[r] = ffma2(p45.x, c2[4], aP[r]);
                aP[r] = ffma2(p45.y, c2[5], aP[r]);
                aP[r] = ffma2(p67.x, c2[6], aP[r]);
                aP[r] = ffma2(p67.y, c2[7], aP[r]);
            }
        }
        #pragma unroll
        for (int r = 0; r < 4; r++) {
            float ta = tanhf(hsum2(aA[r]));
            sm.av_act[g * 4 + r][o] = ta;
            sm.delta[g * 4 + r][o]  = tanhf(hsum2(aP[r])) - ta;
        }
    }

    {   // B5: av_other = tanh([so|act_o] @ W_av_other)  [64,64] (8 grp x 8 rows), chunk 16
        const int o = tid & 63;
        const int g = tid >> 6;              // 0..7
        const float* __restrict__ Wv = W_av_other + o;
        u64 a[8];
        #pragma unroll
        for (int r = 0; r < 8; r++) a[r] = 0ull;
        #pragma unroll 1
        for (int kk = 0; kk < OBS_; kk += 16) {
            float c[16];
            #pragma unroll
            for (int t = 0; t < 16; t++) c[t] = Wv[(kk + t) * DAV_];
            u64 c2[8];
            #pragma unroll
            for (int t = 0; t < 8; t++) c2[t] = pk2(c[2 * t], c[2 * t + 1]);
            #pragma unroll
            for (int r = 0; r < 8; r++) {
                const ulonglong2 s01 = *reinterpret_cast<const ulonglong2*>(&sm.so[g * 8 + r][kk]);
                const ulonglong2 s23 = *reinterpret_cast<const ulonglong2*>(&sm.so[g * 8 + r][kk + 4]);
                const ulonglong2 s45 = *reinterpret_cast<const ulonglong2*>(&sm.so[g * 8 + r][kk + 8]);
                const ulonglong2 s67 = *reinterpret_cast<const ulonglong2*>(&sm.so[g * 8 + r][kk + 12]);
                a[r] = ffma2(s01.x, c2[0], a[r]);
                a[r] = ffma2(s01.y, c2[1], a[r]);
                a[r] = ffma2(s23.x, c2[2], a[r]);
                a[r] = ffma2(s23.y, c2[3], a[r]);
                a[r] = ffma2(s45.x, c2[4], a[r]);
                a[r] = ffma2(s45.y, c2[5], a[r]);
                a[r] = ffma2(s67.x, c2[6], a[r]);
                a[r] = ffma2(s67.y, c2[7], a[r]);
            }
        }
        {
            float c[16];
            #pragma unroll
            for (int t = 0; t < 16; t++) c[t] = Wv[(OBS_ + t) * DAV_];
            u64 c2[8];
            #pragma unroll
            for (int t = 0; t < 8; t++) c2[t] = pk2(c[2 * t], c[2 * t + 1]);
            #pragma unroll
            for (int r = 0; r < 8; r++) {
                const ulonglong2 a01 = *reinterpret_cast<const ulonglong2*>(&sm.act_o[g * 8 + r][0]);
                const ulonglong2 a23 = *reinterpret_cast<const ulonglong2*>(&sm.act_o[g * 8 + r][4]);
                const ulonglong2 a45 = *reinterpret_cast<const ulonglong2*>(&sm.act_o[g * 8 + r][8]);
                const ulonglong2 a67 = *reinterpret_cast<const ulonglong2*>(&sm.act_o[g * 8 + r][12]);
                a[r] = ffma2(a01.x, c2[0], a[r]);
                a[r] = ffma2(a01.y, c2[1], a[r]);
                a[r] = ffma2(a23.x, c2[2], a[r]);
                a[r] = ffma2(a23.y, c2[3], a[r]);
                a[r] = ffma2(a45.x, c2[4], a[r]);
                a[r] = ffma2(a45.y, c2[5], a[r]);
                a[r] = ffma2(a67.x, c2[6], a[r]);
                a[r] = ffma2(a67.y, c2[7], a[r]);
            }
        }
        #pragma unroll
        for (int r = 0; r < 8; r++) sm.av_o[g * 8 + r][o] = tanhf(hsum2(a[r]));
    }
    __syncthreads();

    // ============== Phase P2: both logit GEMMs (register-tiled, f32x2) ==============
    {   // w[i0..i0+1][lane]
        const int j  = lane;
        const int i0 = warp * 2;
        u64 acc[2] = {0ull, 0ull};
        #pragma unroll 4
        for (int d = 0; d < DQK_; d += 4) {
            const ulonglong2 kv = *reinterpret_cast<const ulonglong2*>(&sm.ko_[j][d]);
            #pragma unroll
            for (int c = 0; c < 2; c++) {
                const ulonglong2 qv = *reinterpret_cast<const ulonglong2*>(&sm.qo_[i0 + c][d]);
                acc[c] = ffma2(qv.x, kv.x, acc[c]);
                acc[c] = ffma2(qv.y, kv.y, acc[c]);
            }
        }
        #pragma unroll
        for (int c = 0; c < 2; c++) sm.w[i0 + c][j] = hsum2(acc[c]);
    }
    {   // w_o[i0..i0+1][lane, lane+32]
        const int i0 = warp * 2;
        u64 a0[2] = {0ull, 0ull};
        u64 a1[2] = {0ull, 0ull};
        #pragma unroll 4
        for (int d = 0; d < DQK_; d += 4) {
            const ulonglong2 k0 = *reinterpret_cast<const ulonglong2*>(&sm.keys_o[lane][d]);
            const ulonglong2 k1 = *reinterpret_cast<const ulonglong2*>(&sm.keys_o[lane + 32][d]);
            #pragma unroll
            for (int c = 0; c < 2; c++) {
                const ulonglong2 qv = *reinterpret_cast<const ulonglong2*>(&sm.qa[i0 + c][d]);
                a0[c] = ffma2(qv.x, k0.x, a0[c]);
                a0[c] = ffma2(qv.y, k0.y, a0[c]);
                a1[c] = ffma2(qv.x, k1.x, a1[c]);
                a1[c] = ffma2(qv.y, k1.y, a1[c]);
            }
        }
        #pragma unroll
        for (int c = 0; c < 2; c++) {
            sm.w_o[i0 + c][lane]      = hsum2(a0[c]);
            sm.w_o[i0 + c][lane + 32] = hsum2(a1[c]);
        }
    }
    __syncthreads();

    // ================= Phase P3: both softmaxes (16 warps, 2 rows each) =================
    {
        const int r = warp * 2;
        #pragma unroll
        for (int c = 0; c < 2; c++) {
            float x  = sm.w[r + c][lane];
            float mx = warp_max(x);
            float e  = __expf(x - mx);
            float sv = warp_sum(e);
            float o  = e / sv;
            sm.w[r + c][lane] = o;
            out[OFF_W + b * NN * NN + (r + c) * NN + lane] = o;
        }
        #pragma unroll
        for (int c = 0; c < 2; c++) {
            float x0 = sm.w_o[r + c][lane];
            float x1 = sm.w_o[r + c][lane + 32];
            float mx = warp_max(fmaxf(x0, x1));
            float e0 = __expf(x0 - mx), e1 = __expf(x1 - mx);
            float sv = warp_sum(e0 + e1);
            float o0 = e0 / sv, o1 = e1 / sv;
            sm.w_o[r + c][lane]      = o0;
            sm.w_o[r + c][lane + 32] = o1;
            out[OFF_WO + b * NN * MM + (r + c) * MM + lane]      = o0;
            out[OFF_WO + b * NN * MM + (r + c) * MM + lane + 32] = o1;
        }
    }
    __syncthreads();

    // ======== Phase P4: base = w @ av_act, wav_o = w_o @ av_o (f32x2 pairs) ========
    {
        const int o = tid & 63;
        const int g = tid >> 6;              // 0..7 -> 4 rows each
        u64 a[4] = {0ull, 0ull, 0ull, 0ull};
        #pragma unroll
        for (int kk = 0; kk < NN; kk += 4) {
            const u64 av01 = pk2(sm.av_act[kk + 0][o], sm.av_act[kk + 1][o]);
            const u64 av23 = pk2(sm.av_act[kk + 2][o], sm.av_act[kk + 3][o]);
            #pragma unroll
            for (int r = 0; r < 4; r++) {
                const ulonglong2 w4 = *reinterpret_cast<const ulonglong2*>(&sm.w[g * 4 + r][kk]);
                a[r] = ffma2(w4.x, av01, a[r]);
                a[r] = ffma2(w4.y, av23, a[r]);
            }
        }
        #pragma unroll
        for (int r = 0; r < 4; r++) sm.base_[g * 4 + r][o] = hsum2(a[r]);

        u64 c[4] = {0ull, 0ull, 0ull, 0ull};
        #pragma unroll
        for (int mm = 0; mm < MM; mm += 4) {
            const u64 av01 = pk2(sm.av_o[mm + 0][o], sm.av_o[mm + 1][o]);
            const u64 av23 = pk2(sm.av_o[mm + 2][o], sm.av_o[mm + 3][o]);
            #pragma unroll
            for (int r = 0; r < 4; r++) {
                const ulonglong2 w4 = *reinterpret_cast<const ulonglong2*>(&sm.w_o[g * 4 + r][mm]);
                c[r] = ffma2(w4.x, av01, c[r]);
                c[r] = ffma2(w4.y, av23, c[r]);
            }
        }
        #pragma unroll
        for (int r = 0; r < 4; r++) sm.wav_o[g * 4 + r][o] = hsum2(c[r]);
    }
    __syncthreads();

    // ========= Phase P5: u = [base|wav_o] @ W_f1, v = delta @ W_f1[:64] (f32x2) =========
    {
        const int o = tid & 63;
        const int g = tid >> 6;              // 0..7 -> 4 rows each
        const float* __restrict__ Wf = W_f1 + o;
        u64 aU[4], aV[4];
        #pragma unroll
        for (int r = 0; r < 4; r++) { aU[r] = 0ull; aV[r] = 0ull; }
        #pragma unroll 1
        for (int kk = 0; kk < DAV_; kk += 16) {
            float c[16];
            #pragma unroll
            for (int t = 0; t < 16; t++) c[t] = Wf[(kk + t) * HID_];
            u64 c2[8];
            #pragma unroll
            for (int t = 0; t < 8; t++) c2[t] = pk2(c[2 * t], c[2 * t + 1]);
            #pragma unroll
            for (int r = 0; r < 4; r++) {
                const ulonglong2 b01 = *reinterpret_cast<const ulonglong2*>(&sm.base_[g * 4 + r][kk]);
                const ulonglong2 b23 = *reinterpret_cast<const ulonglong2*>(&sm.base_[g * 4 + r][kk + 4]);
                const ulonglong2 b45 = *reinterpret_cast<const ulonglong2*>(&sm.base_[g * 4 + r][kk + 8]);
                const ulonglong2 b67 = *reinterpret_cast<const ulonglong2*>(&sm.base_[g * 4 + r][kk + 12]);
                const ulonglong2 d01 = *reinterpret_cast<const ulonglong2*>(&sm.delta[g * 4 + r][kk]);
                const ulonglong2 d23 = *reinterpret_cast<const ulonglong2*>(&sm.delta[g * 4 + r][kk + 4]);
                const ulonglong2 d45 = *reinterpret_cast<const ulonglong2*>(&sm.delta[g * 4 + r][kk + 8]);
                const ulonglong2 d67 = *reinterpret_cast<const ulonglong2*>(&sm.delta[g * 4 + r][kk + 12]);
                aU[r] = ffma2(b01.x, c2[0], aU[r]);
                aU[r] = ffma2(b01.y, c2[1], aU[r]);
                aU[r] = ffma2(b23.x, c2[2], aU[r]);
                aU[r] = ffma2(b23.y, c2[3], aU[r]);
                aU[r] = ffma2(b45.x, c2[4], aU[r]);
                aU[r] = ffma2(b45.y, c2[5], aU[r]);
                aU[r] = ffma2(b67.x, c2[6], aU[r]);
                aU[r] = ffma2(b67.y, c2[7], aU[r]);
                aV[r] = ffma2(d01.x, c2[0], aV[r]);
                aV[r] = ffma2(d01.y, c2[1], aV[r]);
                aV[r] = ffma2(d23.x, c2[2], aV[r]);
                aV[r] = ffma2(d23.y, c2[3], aV[r]);
                aV[r] = ffma2(d45.x, c2[4], aV[r]);
                aV[r] = ffma2(d45.y, c2[5], aV[r]);
                aV[r] = ffma2(d67.x, c2[6], aV[r]);
                aV[r] = ffma2(d67.y, c2[7], aV[r]);
            }
        }
        #pragma unroll 1
        for (int kk = 0; kk < DAV_; kk += 16) {
            float c[16];
            #pragma unroll
            for (int t = 0; t < 16; t++) c[t] = Wf[(DAV_ + kk + t) * HID_];
            u64 c2[8];
            #pragma unroll
            for (int t = 0; t < 8; t++) c2[t] = pk2(c[2 * t], c[2 * t + 1]);
            #pragma unroll
            for (int r = 0; r < 4; r++) {
                const ulonglong2 w01 = *reinterpret_cast<const ulonglong2*>(&sm.wav_o[g * 4 + r][kk]);
                const ulonglong2 w23 = *reinterpret_cast<const ulonglong2*>(&sm.wav_o[g * 4 + r][kk + 4]);
                const ulonglong2 w45 = *reinterpret_cast<const ulonglong2*>(&sm.wav_o[g * 4 + r][kk + 8]);
                const ulonglong2 w67 = *reinterpret_cast<const ulonglong2*>(&sm.wav_o[g * 4 + r][kk + 12]);
                aU[r] = ffma2(w01.x, c2[0], aU[r]);
                aU[r] = ffma2(w01.y, c2[1], aU[r]);
                aU[r] = ffma2(w23.x, c2[2], aU[r]);
                aU[r] = ffma2(w23.y, c2[3], aU[r]);
                aU[r] = ffma2(w45.x, c2[4], aU[r]);
                aU[r] = ffma2(w45.y, c2[5], aU[r]);
                aU[r] = ffma2(w67.x, c2[6], aU[r]);
                aU[r] = ffma2(w67.y, c2[7], aU[r]);
            }
        }
        #pragma unroll
        for (int r = 0; r < 4; r++) {
            sm.u[g * 4 + r][o] = hsum2(aU[r]);
            sm.v[g * 4 + r][o] = hsum2(aV[r]);
        }
    }
    __syncthreads();

    // ============== Phase P6: value (register-tiled, scalar leaky-relu path) ==============
    {
        const int j  = lane;
        const int i0 = warp * 2;
        float wij[2], acc[2];
        #pragma unroll
        for (int c = 0; c < 2; c++) { wij[c] = sm.w[i0 + c][j]; acc[c] = 0.f; }
        #pragma unroll 4
        for (int f = 0; f < HID_; f += 4) {
            const float4 v4 = *reinterpret_cast<const float4*>(&sm.v[j][f]);
            const float4 f2 = *reinterpret_cast<const float4*>(&sm.wf2[f]);
            #pragma unroll
            for (int c = 0; c < 2; c++) {
                const float4 u4 = *reinterpret_cast<const float4*>(&sm.u[i0 + c][f]);
                float p, l;
                p = fmaf(wij[c], v4.x, u4.x); l = p > 0.f ? p : 0.01f * p; acc[c] = fmaf(f2.x, l, acc[c]);
                p = fmaf(wij[c], v4.y, u4.y); l = p > 0.f ? p : 0.01f * p; acc[c] = fmaf(f2.y, l, acc[c]);
                p = fmaf(wij[c], v4.z, u4.z); l = p > 0.f ? p : 0.01f * p; acc[c] = fmaf(f2.z, l, acc[c]);
                p = fmaf(wij[c], v4.w, u4.w); l = p > 0.f ? p : 0.01f * p; acc[c] = fmaf(f2.w, l, acc[c]);
            }
        }
        #pragma unroll
        for (int c = 0; c < 2; c++)
            out[OFF_VAL + b * NN * NN + (i0 + c) * NN + j] = acc[c];
    }
}

extern "C" void kernel_launch(void* const* d_in, const int* in_sizes, int n_in,
                              void* d_out, int out_size) {
    const float* states        = (const float*)d_in[0];
    const float* policies      = (const float*)d_in[1];
    const float* actions       = (const float*)d_in[2];
    const float* states_other  = (const float*)d_in[3];
    const float* actions_other = (const float*)d_in[4];
    const float* W_key         = (const float*)d_in[5];
    const float* W_query       = (const float*)d_in[6];
    const float* W_av          = (const float*)d_in[7];
    const float* W_key_other   = (const float*)d_in[8];
    const float* W_query_other = (const float*)d_in[9];
    const float* W_av_other    = (const float*)d_in[10];
    const float* W_f1          = (const float*)d_in[11];
    const float* W_f2          = (const float*)d_in[12];
    float* out = (float*)d_out;

    const int smem_bytes = (int)sizeof(Smem);   // ~221 KB, 1 CTA/SM
    cudaFuncSetAttribute(critic_dual_attn_kernel,
                         cudaFuncAttributeMaxDynamicSharedMemorySize, smem_bytes);

    critic_dual_attn_kernel<<<BB, 512, smem_bytes>>>(
        states, policies, actions, states_other, actions_other,
        W_key, W_query, W_av, W_key_other, W_query_other, W_av_other,
        W_f1, W_f2, out);
}